// round 1
// baseline (speedup 1.0000x reference)
#include <cuda_runtime.h>
#include <math.h>

typedef unsigned long long ull;

#define PITCH   132      // smem row pitch (floats) for 128-wide tiles
#define TPITCH  264      // smem row pitch for the 256-wide MLP hidden tile
#define THREADS 512

// ---------------------------------------------------------------------------
// packed f32x2 helpers (sm_103a): ptxas only emits FFMA2 via PTX fma.rn.f32x2
// ---------------------------------------------------------------------------
__device__ __forceinline__ ull dup2(float x){
    ull r; asm("mov.b64 %0, {%1, %1};" : "=l"(r) : "f"(x)); return r;
}
__device__ __forceinline__ void fma2(ull &d, ull a, ull b){
    asm("fma.rn.f32x2 %0, %1, %2, %0;" : "+l"(d) : "l"(a), "l"(b));
}
__device__ __forceinline__ float2 unpack2(ull v){
    float2 f; asm("mov.b64 {%0, %1}, %2;" : "=f"(f.x), "=f"(f.y) : "l"(v)); return f;
}

// ---------------------------------------------------------------------------
// Register-blocked GEMM tile: res[TM][TN] = A[r0..r0+TM][0..KD) @ W[0..KD)[c0..c0+TN)
// A in smem (pitch apitch), W in global row-major (pitch wpitch).
// Weight columns packed in pairs (LDG.128 delivers them pre-packed); activation
// scalar duplicated into both f32x2 lanes.
// ---------------------------------------------------------------------------
template<int KD, int TM, int TN>
__device__ __forceinline__ void gemm_tile(const float* __restrict__ As, int apitch, int r0,
                                          const float* __restrict__ W, int wpitch, int c0,
                                          float (&res)[TM][TN])
{
    static_assert(TN % 4 == 0, "TN must be multiple of 4");
    ull acc[TM][TN/2];
#pragma unroll
    for (int m = 0; m < TM; m++)
#pragma unroll
        for (int j = 0; j < TN/2; j++) acc[m][j] = 0ull;

    const float* a[TM];
#pragma unroll
    for (int m = 0; m < TM; m++) a[m] = As + (r0 + m) * apitch;
    const float* wrow = W + c0;

#pragma unroll 4
    for (int k = 0; k < KD; k++){
        ull ad[TM];
#pragma unroll
        for (int m = 0; m < TM; m++) ad[m] = dup2(a[m][k]);
#pragma unroll
        for (int jj = 0; jj < TN/4; jj++){
            ulonglong2 wv = *(const ulonglong2*)(wrow + jj * 4);   // LDG.128 -> 2 packed col-pairs
#pragma unroll
            for (int m = 0; m < TM; m++){
                fma2(acc[m][2*jj],   ad[m], wv.x);
                fma2(acc[m][2*jj+1], ad[m], wv.y);
            }
        }
        wrow += wpitch;
    }
#pragma unroll
    for (int m = 0; m < TM; m++)
#pragma unroll
        for (int j = 0; j < TN/2; j++){
            float2 f = unpack2(acc[m][j]);
            res[m][2*j]   = f.x;
            res[m][2*j+1] = f.y;
        }
}

// ---------------------------------------------------------------------------
// LayerNorm over 128 cols: 8 threads per row, shfl reduction within 8-lane groups
// ---------------------------------------------------------------------------
__device__ __forceinline__ void layernorm(const float* __restrict__ Xs, float* __restrict__ Ns,
                                          const float* __restrict__ g, const float* __restrict__ b,
                                          int tid)
{
    const int row = tid >> 3, sub = tid & 7;
    const float* xr = Xs + row * PITCH;
    float s = 0.f, s2 = 0.f;
#pragma unroll
    for (int i = 0; i < 16; i++){
        float v = xr[sub + i * 8];
        s += v; s2 = fmaf(v, v, s2);
    }
#pragma unroll
    for (int o = 4; o; o >>= 1){
        s  += __shfl_xor_sync(0xffffffffu, s,  o);
        s2 += __shfl_xor_sync(0xffffffffu, s2, o);
    }
    float mu  = s  * (1.f / 128.f);
    float var = s2 * (1.f / 128.f) - mu * mu;
    float rs  = rsqrtf(var + 1e-5f);
    float* nr = Ns + row * PITCH;
#pragma unroll
    for (int i = 0; i < 16; i++){
        int c = sub + i * 8;
        nr[c] = (xr[c] - mu) * rs * g[c] + b[c];
    }
}

// ---------------------------------------------------------------------------
// Windowed attention: warp w handles head w/2, query rows (w&1)*32 + lane.
// Online softmax, k/v rows broadcast from smem (float4, conflict-free).
// Output written back into Qs (q no longer needed).
// ---------------------------------------------------------------------------
__device__ __forceinline__ void attention_phase(float* Qs, const float* Ks, const float* Vs, int tid)
{
    const int w    = tid >> 5;
    const int lane = tid & 31;
    const int h    = w >> 1;
    const int qi   = ((w & 1) << 5) | lane;
    const int co   = h * 16;

    const float* qr = Qs + qi * PITCH + co;
    float4 qa = *(const float4*)(qr);
    float4 qb = *(const float4*)(qr + 4);
    float4 qc = *(const float4*)(qr + 8);
    float4 qd = *(const float4*)(qr + 12);

    float4 oa = make_float4(0.f,0.f,0.f,0.f), ob = oa, oc = oa, od = oa;
    float m = -1e30f, l = 0.f;

    for (int j = 0; j < 64; j++){
        const float* kr = Ks + j * PITCH + co;
        float4 ka = *(const float4*)(kr);
        float4 kb = *(const float4*)(kr + 4);
        float4 kc = *(const float4*)(kr + 8);
        float4 kd = *(const float4*)(kr + 12);
        float s;
        s = qa.x * ka.x;          s = fmaf(qa.y, ka.y, s);
        s = fmaf(qa.z, ka.z, s);  s = fmaf(qa.w, ka.w, s);
        s = fmaf(qb.x, kb.x, s);  s = fmaf(qb.y, kb.y, s);
        s = fmaf(qb.z, kb.z, s);  s = fmaf(qb.w, kb.w, s);
        s = fmaf(qc.x, kc.x, s);  s = fmaf(qc.y, kc.y, s);
        s = fmaf(qc.z, kc.z, s);  s = fmaf(qc.w, kc.w, s);
        s = fmaf(qd.x, kd.x, s);  s = fmaf(qd.y, kd.y, s);
        s = fmaf(qd.z, kd.z, s);  s = fmaf(qd.w, kd.w, s);
        s *= 0.25f;                               // HD^-0.5 = 16^-0.5

        float mn   = fmaxf(m, s);
        float corr = __expf(m - mn);
        float pz   = __expf(s - mn);
        l = fmaf(l, corr, pz);
        m = mn;

        const float* vr = Vs + j * PITCH + co;
        float4 va = *(const float4*)(vr);
        float4 vb = *(const float4*)(vr + 4);
        float4 vc = *(const float4*)(vr + 8);
        float4 vd = *(const float4*)(vr + 12);
        oa.x = fmaf(oa.x, corr, pz * va.x);  oa.y = fmaf(oa.y, corr, pz * va.y);
        oa.z = fmaf(oa.z, corr, pz * va.z);  oa.w = fmaf(oa.w, corr, pz * va.w);
        ob.x = fmaf(ob.x, corr, pz * vb.x);  ob.y = fmaf(ob.y, corr, pz * vb.y);
        ob.z = fmaf(ob.z, corr, pz * vb.z);  ob.w = fmaf(ob.w, corr, pz * vb.w);
        oc.x = fmaf(oc.x, corr, pz * vc.x);  oc.y = fmaf(oc.y, corr, pz * vc.y);
        oc.z = fmaf(oc.z, corr, pz * vc.z);  oc.w = fmaf(oc.w, corr, pz * vc.w);
        od.x = fmaf(od.x, corr, pz * vd.x);  od.y = fmaf(od.y, corr, pz * vd.y);
        od.z = fmaf(od.z, corr, pz * vd.z);  od.w = fmaf(od.w, corr, pz * vd.w);
    }
    float inv = 1.0f / l;
    float* orow = Qs + qi * PITCH + co;
    *(float4*)(orow)      = make_float4(oa.x*inv, oa.y*inv, oa.z*inv, oa.w*inv);
    *(float4*)(orow + 4)  = make_float4(ob.x*inv, ob.y*inv, ob.z*inv, ob.w*inv);
    *(float4*)(orow + 8)  = make_float4(oc.x*inv, oc.y*inv, oc.z*inv, oc.w*inv);
    *(float4*)(orow + 12) = make_float4(od.x*inv, od.y*inv, od.z*inv, od.w*inv);
}

// ---------------------------------------------------------------------------
// Fused transformer block: one CTA = one 64-token window. All intermediates in smem.
// ---------------------------------------------------------------------------
extern __shared__ float smbuf[];

__global__ void __launch_bounds__(THREADS, 1)
fused_block_kernel(const float* __restrict__ feats,
                   const float* __restrict__ w_pre,  const float* __restrict__ b_pre,
                   const float* __restrict__ g1,     const float* __restrict__ b1,
                   const float* __restrict__ w_qkv,  const float* __restrict__ b_qkv,
                   const float* __restrict__ w_proj, const float* __restrict__ b_proj,
                   const float* __restrict__ g2,     const float* __restrict__ b2,
                   const float* __restrict__ w_m1,   const float* __restrict__ b_m1,
                   const float* __restrict__ w_m2,   const float* __restrict__ b_m2,
                   const float* __restrict__ w_post, const float* __restrict__ b_post,
                   float* __restrict__ out)
{
    float* Xs = smbuf;                  // residual stream x2  [64][132]
    float* Ns = smbuf + 64 * PITCH;     // LN output / feats staging
    float* Qs = smbuf + 2 * 64 * PITCH; // q, later attention output o
    float* Ks = smbuf + 3 * 64 * PITCH; // k, later MLP hidden t (pitch 264 spans Ks+Vs)
    float* Vs = smbuf + 4 * 64 * PITCH; // v
    float* Ts = Ks;

    const int tid = threadIdx.x;
    const size_t tok0 = (size_t)blockIdx.x * 64;

    // stage feats tile [64][64] into Ns cols 0..63
    for (int i = tid; i < 64 * 16; i += THREADS){
        int t = i >> 4, c4 = i & 15;
        float4 v = ((const float4*)(feats + (tok0 + t) * 64))[c4];
        *(float4*)(Ns + t * PITCH + c4 * 4) = v;
    }
    __syncthreads();

    const int cg = tid & 15, tq = tid >> 4;   // default mapping: 16 col-groups x 32 row-pairs
    const int r0 = tq * 2;

    // ---- pre: x2 = feats @ w_pre + b_pre ----
    {
        int c0 = cg * 8;
        float res[2][8];
        gemm_tile<64,2,8>(Ns, PITCH, r0, w_pre, 128, c0, res);
#pragma unroll
        for (int m = 0; m < 2; m++)
#pragma unroll
            for (int j = 0; j < 8; j++)
                Xs[(r0+m)*PITCH + c0 + j] = res[m][j] + b_pre[c0 + j];
    }
    __syncthreads();
    layernorm(Xs, Ns, g1, b1, tid);
    __syncthreads();

    // ---- qkv = n1 @ w_qkv + b_qkv  (3 x 128-col GEMMs) ----
    {
        int c0 = cg * 8;
        float res[2][8];
        gemm_tile<128,2,8>(Ns, PITCH, r0, w_qkv, 384, c0, res);
#pragma unroll
        for (int m = 0; m < 2; m++)
#pragma unroll
            for (int j = 0; j < 8; j++)
                Qs[(r0+m)*PITCH + c0 + j] = res[m][j] + b_qkv[c0 + j];

        gemm_tile<128,2,8>(Ns, PITCH, r0, w_qkv + 128, 384, c0, res);
#pragma unroll
        for (int m = 0; m < 2; m++)
#pragma unroll
            for (int j = 0; j < 8; j++)
                Ks[(r0+m)*PITCH + c0 + j] = res[m][j] + b_qkv[128 + c0 + j];

        gemm_tile<128,2,8>(Ns, PITCH, r0, w_qkv + 256, 384, c0, res);
#pragma unroll
        for (int m = 0; m < 2; m++)
#pragma unroll
            for (int j = 0; j < 8; j++)
                Vs[(r0+m)*PITCH + c0 + j] = res[m][j] + b_qkv[256 + c0 + j];
    }
    __syncthreads();

    attention_phase(Qs, Ks, Vs, tid);
    __syncthreads();

    // ---- proj + residual: x2 += o @ w_proj + b_proj ----
    {
        int c0 = cg * 8;
        float res[2][8];
        gemm_tile<128,2,8>(Qs, PITCH, r0, w_proj, 128, c0, res);
#pragma unroll
        for (int m = 0; m < 2; m++)
#pragma unroll
            for (int j = 0; j < 8; j++)
                Xs[(r0+m)*PITCH + c0 + j] += res[m][j] + b_proj[c0 + j];
    }
    __syncthreads();
    layernorm(Xs, Ns, g2, b2, tid);
    __syncthreads();

    // ---- mlp1: t = gelu(n2 @ w_m1 + b_m1)  (256 cols, TM=4) ----
    {
        int cg2 = tid & 31, tq2 = tid >> 5;
        int rr0 = tq2 * 4, c0 = cg2 * 8;
        float res[4][8];
        gemm_tile<128,4,8>(Ns, PITCH, rr0, w_m1, 256, c0, res);
#pragma unroll
        for (int m = 0; m < 4; m++)
#pragma unroll
            for (int j = 0; j < 8; j++){
                float x = res[m][j] + b_m1[c0 + j];
                Ts[(rr0+m)*TPITCH + c0 + j] = 0.5f * x * (1.0f + erff(x * 0.70710678118654752f));
            }
    }
    __syncthreads();

    // ---- mlp2 + residual: x2 += t @ w_m2 + b_m2  (K=256) ----
    {
        int c0 = cg * 8;
        float res[2][8];
        gemm_tile<256,2,8>(Ts, TPITCH, r0, w_m2, 128, c0, res);
#pragma unroll
        for (int m = 0; m < 2; m++)
#pragma unroll
            for (int j = 0; j < 8; j++)
                Xs[(r0+m)*PITCH + c0 + j] += res[m][j] + b_m2[c0 + j];
    }
    __syncthreads();

    // ---- post: out = x2 @ w_post + b_post  (64 cols, TN=4) ----
    {
        int c0 = cg * 4;
        float res[2][4];
        gemm_tile<128,2,4>(Xs, PITCH, r0, w_post, 64, c0, res);
#pragma unroll
        for (int m = 0; m < 2; m++){
            float4 v = make_float4(res[m][0] + b_post[c0],
                                   res[m][1] + b_post[c0 + 1],
                                   res[m][2] + b_post[c0 + 2],
                                   res[m][3] + b_post[c0 + 3]);
            *(float4*)(out + (tok0 + r0 + m) * 64 + c0) = v;
        }
    }
}

extern "C" void kernel_launch(void* const* d_in, const int* in_sizes, int n_in,
                              void* d_out, int out_size)
{
    const float* feats  = (const float*)d_in[0];
    const float* w_pre  = (const float*)d_in[1];
    const float* b_pre  = (const float*)d_in[2];
    const float* g1     = (const float*)d_in[3];
    const float* b1     = (const float*)d_in[4];
    const float* w_qkv  = (const float*)d_in[5];
    const float* b_qkv  = (const float*)d_in[6];
    const float* w_proj = (const float*)d_in[7];
    const float* b_proj = (const float*)d_in[8];
    const float* g2     = (const float*)d_in[9];
    const float* b2     = (const float*)d_in[10];
    const float* w_m1   = (const float*)d_in[11];
    const float* b_m1   = (const float*)d_in[12];
    const float* w_m2   = (const float*)d_in[13];
    const float* b_m2   = (const float*)d_in[14];
    const float* w_post = (const float*)d_in[15];
    const float* b_post = (const float*)d_in[16];
    float* out = (float*)d_out;

    const int ntok    = in_sizes[0] / 64;   // C = 64
    const int nblocks = ntok / 64;          // PS = 64 tokens per window
    const size_t smem = (size_t)5 * 64 * PITCH * sizeof(float);   // 168960 B

    cudaFuncSetAttribute(fused_block_kernel,
                         cudaFuncAttributeMaxDynamicSharedMemorySize, (int)smem);

    fused_block_kernel<<<nblocks, THREADS, smem>>>(feats, w_pre, b_pre, g1, b1,
                                                   w_qkv, b_qkv, w_proj, b_proj,
                                                   g2, b2, w_m1, b_m1, w_m2, b_m2,
                                                   w_post, b_post, out);
}

// round 2
// speedup vs baseline: 1.4609x; 1.4609x over previous
#include <cuda_runtime.h>
#include <math.h>

typedef unsigned long long ull;

#define PITCH   132      // smem row pitch (floats) for 128-wide tiles (LDS.128 conflict-free)
#define TPITCH  260      // smem row pitch for the 256-wide MLP hidden tile (4r+k banks)
#define THREADS 512

// ---------------------------------------------------------------------------
// packed f32x2 helpers (sm_103a)
// ---------------------------------------------------------------------------
__device__ __forceinline__ ull dup2(float x){
    ull r; asm("mov.b64 %0, {%1, %1};" : "=l"(r) : "f"(x)); return r;
}
__device__ __forceinline__ void fma2(ull &d, ull a, ull b){
    asm("fma.rn.f32x2 %0, %1, %2, %0;" : "+l"(d) : "l"(a), "l"(b));
}
__device__ __forceinline__ ull mul2(ull a, ull b){
    ull d; asm("mul.rn.f32x2 %0, %1, %2;" : "=l"(d) : "l"(a), "l"(b)); return d;
}
__device__ __forceinline__ float2 unpack2(ull v){
    float2 f; asm("mov.b64 {%0, %1}, %2;" : "=f"(f.x), "=f"(f.y) : "l"(v)); return f;
}

// ---------------------------------------------------------------------------
// Warp-level GEMM tile.
//   warp covers 64 rows x (NW * TN) cols; thread = rows {r, r+32}, cols
//   c0..c0+TN-1 (+ w*wstep for NW fused weight blocks sharing activations).
//   Weight loads: all lanes same address -> L1 broadcast (1 sector).
//   Activation loads: LDS.128 over k, conflict-free (pitch % 4 == 0, 4r+k banks).
// ---------------------------------------------------------------------------
template<int KD, int TN, int NW>
__device__ __forceinline__ void gemm_warp(const float* __restrict__ As, int apitch, int r,
                                          const float* __restrict__ W, int wpitch,
                                          int c0, int wstep,
                                          float (&res)[NW][2][TN])
{
    static_assert(TN % 4 == 0 && KD % 4 == 0, "");
    ull acc[NW][2][TN/2];
#pragma unroll
    for (int w = 0; w < NW; w++)
#pragma unroll
        for (int m = 0; m < 2; m++)
#pragma unroll
            for (int j = 0; j < TN/2; j++) acc[w][m][j] = 0ull;

    const float* a0p = As + r * apitch;
    const float* a1p = As + (r + 32) * apitch;

#pragma unroll 2
    for (int k = 0; k < KD; k += 4){
        float4 a0 = *(const float4*)(a0p + k);
        float4 a1 = *(const float4*)(a1p + k);
        float a0v[4] = {a0.x, a0.y, a0.z, a0.w};
        float a1v[4] = {a1.x, a1.y, a1.z, a1.w};
#pragma unroll
        for (int kk = 0; kk < 4; kk++){
            ull d0 = dup2(a0v[kk]);
            ull d1 = dup2(a1v[kk]);
            const float* wrow = W + (size_t)(k + kk) * wpitch + c0;
#pragma unroll
            for (int w = 0; w < NW; w++){
                const float* wr = wrow + w * wstep;
#pragma unroll
                for (int j = 0; j < TN/4; j++){
                    ulonglong2 wv = *(const ulonglong2*)(wr + 4 * j);   // broadcast LDG.128
                    fma2(acc[w][0][2*j],   d0, wv.x);
                    fma2(acc[w][0][2*j+1], d0, wv.y);
                    fma2(acc[w][1][2*j],   d1, wv.x);
                    fma2(acc[w][1][2*j+1], d1, wv.y);
                }
            }
        }
    }
#pragma unroll
    for (int w = 0; w < NW; w++)
#pragma unroll
        for (int m = 0; m < 2; m++)
#pragma unroll
            for (int j = 0; j < TN/2; j++){
                float2 f = unpack2(acc[w][m][j]);
                res[w][m][2*j]   = f.x;
                res[w][m][2*j+1] = f.y;
            }
}

// ---------------------------------------------------------------------------
// LayerNorm over 128 cols: 8 threads per row, shfl reduction
// ---------------------------------------------------------------------------
__device__ __forceinline__ void layernorm(const float* __restrict__ Xs, float* __restrict__ Ns,
                                          const float* __restrict__ g, const float* __restrict__ b,
                                          int tid)
{
    const int row = tid >> 3, sub = tid & 7;
    const float* xr = Xs + row * PITCH;
    float s = 0.f, s2 = 0.f;
#pragma unroll
    for (int i = 0; i < 16; i++){
        float v = xr[sub + i * 8];
        s += v; s2 = fmaf(v, v, s2);
    }
#pragma unroll
    for (int o = 4; o; o >>= 1){
        s  += __shfl_xor_sync(0xffffffffu, s,  o);
        s2 += __shfl_xor_sync(0xffffffffu, s2, o);
    }
    float mu  = s  * (1.f / 128.f);
    float var = s2 * (1.f / 128.f) - mu * mu;
    float rs  = rsqrtf(var + 1e-5f);
    float* nr = Ns + row * PITCH;
#pragma unroll
    for (int i = 0; i < 16; i++){
        int c = sub + i * 8;
        nr[c] = (xr[c] - mu) * rs * g[c] + b[c];
    }
}

// ---------------------------------------------------------------------------
// Windowed attention: warp w -> head w/2, query row (w&1)*32 + lane.
// Online softmax; dot and o-update packed with f32x2. Output overwrites Qs.
// ---------------------------------------------------------------------------
__device__ __forceinline__ void attention_phase(float* Qs, const float* Ks, const float* Vs, int tid)
{
    const int w    = tid >> 5;
    const int lane = tid & 31;
    const int h    = w >> 1;
    const int qi   = ((w & 1) << 5) | lane;
    const int co   = h * 16;

    const ull* qp = (const ull*)(Qs + qi * PITCH + co);   // 8 packed pairs (16 floats)
    ull q[8];
#pragma unroll
    for (int i = 0; i < 8; i++) q[i] = qp[i];

    ull o[8];
#pragma unroll
    for (int i = 0; i < 8; i++) o[i] = 0ull;
    float m = -1e30f, l = 0.f;

    for (int j = 0; j < 64; j++){
        const ull* kp = (const ull*)(Ks + j * PITCH + co);
        ull accd = 0ull;
#pragma unroll
        for (int i = 0; i < 8; i++) fma2(accd, q[i], kp[i]);
        float2 df = unpack2(accd);
        float s = (df.x + df.y) * 0.25f;              // HD^-0.5 = 0.25

        float mn   = fmaxf(m, s);
        float corr = __expf(m - mn);
        float pz   = __expf(s - mn);
        l = fmaf(l, corr, pz);
        m = mn;

        ull cd = dup2(corr);
        ull pd = dup2(pz);
        const ull* vp = (const ull*)(Vs + j * PITCH + co);
#pragma unroll
        for (int i = 0; i < 8; i++){
            ull t = mul2(pd, vp[i]);    // pz * v
            fma2(t, o[i], cd);          // += o * corr
            o[i] = t;
        }
    }
    ull inv = dup2(1.0f / l);
    ull* orow = (ull*)(Qs + qi * PITCH + co);
#pragma unroll
    for (int i = 0; i < 8; i++) orow[i] = mul2(o[i], inv);
}

// ---------------------------------------------------------------------------
// Fused transformer block: one CTA = one 64-token window.
// ---------------------------------------------------------------------------
extern __shared__ float smbuf[];

__global__ void __launch_bounds__(THREADS, 1)
fused_block_kernel(const float* __restrict__ feats,
                   const float* __restrict__ w_pre,  const float* __restrict__ b_pre,
                   const float* __restrict__ g1,     const float* __restrict__ b1,
                   const float* __restrict__ w_qkv,  const float* __restrict__ b_qkv,
                   const float* __restrict__ w_proj, const float* __restrict__ b_proj,
                   const float* __restrict__ g2,     const float* __restrict__ b2,
                   const float* __restrict__ w_m1,   const float* __restrict__ b_m1,
                   const float* __restrict__ w_m2,   const float* __restrict__ b_m2,
                   const float* __restrict__ w_post, const float* __restrict__ b_post,
                   float* __restrict__ out)
{
    float* Xs = smbuf;                  // residual stream x2  [64][132]
    float* Ns = smbuf + 64 * PITCH;     // LN output / feats staging
    float* Qs = smbuf + 2 * 64 * PITCH; // q, later attention output o
    float* Ks = smbuf + 3 * 64 * PITCH; // k; later MLP hidden (pitch 260 spans Ks+Vs)
    float* Vs = smbuf + 4 * 64 * PITCH; // v
    float* Ts = Ks;

    const int tid  = threadIdx.x;
    const int warp = tid >> 5;
    const int lane = tid & 31;
    const size_t tok0 = (size_t)blockIdx.x * 64;

    // stage feats tile [64][64] into Ns cols 0..63
    for (int i = tid; i < 64 * 16; i += THREADS){
        int t = i >> 4, c4 = i & 15;
        float4 v = ((const float4*)(feats + (tok0 + t) * 64))[c4];
        *(float4*)(Ns + t * PITCH + c4 * 4) = v;
    }
    __syncthreads();

    // ---- pre: x2 = feats @ w_pre + b_pre ----  (64 -> 128)
    {
        int c0 = warp * 8;
        float res[1][2][8];
        gemm_warp<64, 8, 1>(Ns, PITCH, lane, w_pre, 128, c0, 0, res);
#pragma unroll
        for (int mm = 0; mm < 2; mm++)
#pragma unroll
            for (int j = 0; j < 8; j++)
                Xs[(lane + mm*32) * PITCH + c0 + j] = res[0][mm][j] + b_pre[c0 + j];
    }
    __syncthreads();
    layernorm(Xs, Ns, g1, b1, tid);
    __syncthreads();

    // ---- qkv = n1 @ w_qkv + b_qkv  (fused: 3 weight blocks share activations) ----
    {
        int c0 = warp * 8;
        float res[3][2][8];
        gemm_warp<128, 8, 3>(Ns, PITCH, lane, w_qkv, 384, c0, 128, res);
        float* dst[3] = {Qs, Ks, Vs};
#pragma unroll
        for (int w = 0; w < 3; w++)
#pragma unroll
            for (int mm = 0; mm < 2; mm++)
#pragma unroll
                for (int j = 0; j < 8; j++)
                    dst[w][(lane + mm*32) * PITCH + c0 + j] =
                        res[w][mm][j] + b_qkv[w * 128 + c0 + j];
    }
    __syncthreads();

    attention_phase(Qs, Ks, Vs, tid);
    __syncthreads();

    // ---- proj + residual: x2 += o @ w_proj + b_proj ----
    {
        int c0 = warp * 8;
        float res[1][2][8];
        gemm_warp<128, 8, 1>(Qs, PITCH, lane, w_proj, 128, c0, 0, res);
#pragma unroll
        for (int mm = 0; mm < 2; mm++)
#pragma unroll
            for (int j = 0; j < 8; j++)
                Xs[(lane + mm*32) * PITCH + c0 + j] += res[0][mm][j] + b_proj[c0 + j];
    }
    __syncthreads();
    layernorm(Xs, Ns, g2, b2, tid);
    __syncthreads();

    // ---- mlp1: t = gelu(n2 @ w_m1 + b_m1)  (128 -> 256, TN=16) ----
    {
        int c0 = warp * 16;
        float res[1][2][16];
        gemm_warp<128, 16, 1>(Ns, PITCH, lane, w_m1, 256, c0, 0, res);
#pragma unroll
        for (int mm = 0; mm < 2; mm++)
#pragma unroll
            for (int j = 0; j < 16; j++){
                float x = res[0][mm][j] + b_m1[c0 + j];
                Ts[(lane + mm*32) * TPITCH + c0 + j] =
                    0.5f * x * (1.0f + erff(x * 0.70710678118654752f));
            }
    }
    __syncthreads();

    // ---- mlp2 + residual: x2 += t @ w_m2 + b_m2  (256 -> 128) ----
    {
        int c0 = warp * 8;
        float res[1][2][8];
        gemm_warp<256, 8, 1>(Ts, TPITCH, lane, w_m2, 128, c0, 0, res);
#pragma unroll
        for (int mm = 0; mm < 2; mm++)
#pragma unroll
            for (int j = 0; j < 8; j++)
                Xs[(lane + mm*32) * PITCH + c0 + j] += res[0][mm][j] + b_m2[c0 + j];
    }
    __syncthreads();

    // ---- post: out = x2 @ w_post + b_post  (128 -> 64, TN=4, all 16 warps) ----
    {
        int c0 = warp * 4;
        float res[1][2][4];
        gemm_warp<128, 4, 1>(Xs, PITCH, lane, w_post, 64, c0, 0, res);
#pragma unroll
        for (int mm = 0; mm < 2; mm++){
            int row = lane + mm * 32;
            float4 v = make_float4(res[0][mm][0] + b_post[c0],
                                   res[0][mm][1] + b_post[c0 + 1],
                                   res[0][mm][2] + b_post[c0 + 2],
                                   res[0][mm][3] + b_post[c0 + 3]);
            *(float4*)(out + (tok0 + row) * 64 + c0) = v;
        }
    }
}

extern "C" void kernel_launch(void* const* d_in, const int* in_sizes, int n_in,
                              void* d_out, int out_size)
{
    const float* feats  = (const float*)d_in[0];
    const float* w_pre  = (const float*)d_in[1];
    const float* b_pre  = (const float*)d_in[2];
    const float* g1     = (const float*)d_in[3];
    const float* b1     = (const float*)d_in[4];
    const float* w_qkv  = (const float*)d_in[5];
    const float* b_qkv  = (const float*)d_in[6];
    const float* w_proj = (const float*)d_in[7];
    const float* b_proj = (const float*)d_in[8];
    const float* g2     = (const float*)d_in[9];
    const float* b2     = (const float*)d_in[10];
    const float* w_m1   = (const float*)d_in[11];
    const float* b_m1   = (const float*)d_in[12];
    const float* w_m2   = (const float*)d_in[13];
    const float* b_m2   = (const float*)d_in[14];
    const float* w_post = (const float*)d_in[15];
    const float* b_post = (const float*)d_in[16];
    float* out = (float*)d_out;

    const int ntok    = in_sizes[0] / 64;   // C = 64
    const int nblocks = ntok / 64;          // PS = 64 tokens per window
    const size_t smem = (size_t)5 * 64 * PITCH * sizeof(float);   // 168960 B

    cudaFuncSetAttribute(fused_block_kernel,
                         cudaFuncAttributeMaxDynamicSharedMemorySize, (int)smem);

    fused_block_kernel<<<nblocks, THREADS, smem>>>(feats, w_pre, b_pre, g1, b1,
                                                   w_qkv, b_qkv, w_proj, b_proj,
                                                   g2, b2, w_m1, b_m1, w_m2, b_m2,
                                                   w_post, b_post, out);
}